// round 1
// baseline (speedup 1.0000x reference)
#include <cuda_runtime.h>
#include <math.h>

#define Bb   2
#define Tt   2048
#define Dd   1024
#define Hh   16
#define Kh   64
#define FF   4096
#define MR   (Bb*Tt)   // 4096 rows

// ---------------- scratch (static device globals; no allocation) ----------------
__device__ float g_h  [MR*Dd];   // LN1 output
__device__ float g_q  [MR*Dd];   // [B,H,T,K]
__device__ float g_k  [MR*Dd];
__device__ float g_v  [MR*Dd];
__device__ float g_o  [MR*Dd];   // attention out [B,H,T,K]
__device__ float g_oc [MR*Dd];   // concat [B,T,D]
__device__ float g_x1 [MR*Dd];   // after attention residual
__device__ float g_h2 [MR*Dd];   // LN2 output
__device__ float g_ff [MR*FF];   // FFN hidden (64 MB)

// ---------------- LayerNorm: one block per row, 256 threads ----------------
__global__ void ln_kernel(const float* __restrict__ x, const float* __restrict__ g,
                          const float* __restrict__ be, float* __restrict__ out) {
    __shared__ float red[256];
    int row = blockIdx.x;
    int tid = threadIdx.x;
    const float* xr = x + (size_t)row * Dd;

    float v[4];
    float s = 0.f;
#pragma unroll
    for (int i = 0; i < 4; i++) { v[i] = xr[tid + 256*i]; s += v[i]; }

    red[tid] = s; __syncthreads();
    for (int o = 128; o > 0; o >>= 1) { if (tid < o) red[tid] += red[tid + o]; __syncthreads(); }
    float mu = red[0] * (1.f / Dd);
    __syncthreads();

    float sq = 0.f;
#pragma unroll
    for (int i = 0; i < 4; i++) { float d = v[i] - mu; sq += d * d; }
    red[tid] = sq; __syncthreads();
    for (int o = 128; o > 0; o >>= 1) { if (tid < o) red[tid] += red[tid + o]; __syncthreads(); }
    float rstd = rsqrtf(red[0] * (1.f / Dd) + 1e-5f);

    float* orow = out + (size_t)row * Dd;
#pragma unroll
    for (int i = 0; i < 4; i++) {
        int c = tid + 256*i;
        orow[c] = (v[i] - mu) * rstd * g[c] + be[c];
    }
}

// ---------------- generic fp32 GEMM: C = A[MxK] @ B[KxN] (+bias)(+resid)(+gelu) ----------------
// mode bit0: +bias[col], bit1: +resid[row*N+col], bit2: exact GELU
__global__ void gemm_kernel(const float* __restrict__ A, const float* __restrict__ Bm,
                            const float* __restrict__ bias, const float* __restrict__ resid,
                            float* __restrict__ C, int M, int N, int Kd, int mode) {
    __shared__ float As[16][65];
    __shared__ float Bs[16][64];
    int tid = threadIdx.x;
    int tx = tid & 15, ty = tid >> 4;
    int bn = blockIdx.x * 64, bm = blockIdx.y * 64;

    float acc[4][4] = {};

    int ac = tid & 15, ar = tid >> 4;   // A loader: col (k), row base
    int bc = tid & 63, br = tid >> 6;   // B loader: col (n), row base (k)

    for (int k0 = 0; k0 < Kd; k0 += 16) {
#pragma unroll
        for (int i = 0; i < 4; i++)
            As[ac][ar + 16*i] = A[(size_t)(bm + ar + 16*i) * Kd + k0 + ac];
#pragma unroll
        for (int i = 0; i < 4; i++)
            Bs[br + 4*i][bc] = Bm[(size_t)(k0 + br + 4*i) * N + bn + bc];
        __syncthreads();
#pragma unroll
        for (int kk = 0; kk < 16; kk++) {
            float a[4], b[4];
#pragma unroll
            for (int i = 0; i < 4; i++) a[i] = As[kk][ty*4 + i];
#pragma unroll
            for (int j = 0; j < 4; j++) b[j] = Bs[kk][tx*4 + j];
#pragma unroll
            for (int i = 0; i < 4; i++)
#pragma unroll
                for (int j = 0; j < 4; j++) acc[i][j] += a[i] * b[j];
        }
        __syncthreads();
    }

#pragma unroll
    for (int i = 0; i < 4; i++) {
        int r = bm + ty*4 + i;
#pragma unroll
        for (int j = 0; j < 4; j++) {
            int c = bn + tx*4 + j;
            float vv = acc[i][j];
            if (mode & 1) vv += bias[c];
            if (mode & 2) vv += resid[(size_t)r * N + c];
            if (mode & 4) vv = 0.5f * vv * (1.f + erff(vv * 0.70710678118654752f));
            C[(size_t)r * N + c] = vv;
        }
    }
}

// ---------------- QKV projection: per-head W [H, D, 64]; output [B,H,T,K] ----------------
// grid: (H, MR/64, 3); block 256
__global__ void qkv_kernel(const float* __restrict__ A,
                           const float* __restrict__ Wq, const float* __restrict__ Wk,
                           const float* __restrict__ Wv) {
    __shared__ float As[16][65];
    __shared__ float Bs[16][64];
    int which = blockIdx.z;
    const float* W = (which == 0) ? Wq : (which == 1) ? Wk : Wv;
    float* out     = (which == 0) ? g_q : (which == 1) ? g_k : g_v;

    int h = blockIdx.x;
    int bm = blockIdx.y * 64;
    const float* Bm = W + (size_t)h * Dd * Kh;   // [D x 64], ld = 64

    int tid = threadIdx.x;
    int tx = tid & 15, ty = tid >> 4;
    float acc[4][4] = {};

    int ac = tid & 15, ar = tid >> 4;
    int bc = tid & 63, br = tid >> 6;

    for (int k0 = 0; k0 < Dd; k0 += 16) {
#pragma unroll
        for (int i = 0; i < 4; i++)
            As[ac][ar + 16*i] = A[(size_t)(bm + ar + 16*i) * Dd + k0 + ac];
#pragma unroll
        for (int i = 0; i < 4; i++)
            Bs[br + 4*i][bc] = Bm[(size_t)(k0 + br + 4*i) * 64 + bc];
        __syncthreads();
#pragma unroll
        for (int kk = 0; kk < 16; kk++) {
            float a[4], b[4];
#pragma unroll
            for (int i = 0; i < 4; i++) a[i] = As[kk][ty*4 + i];
#pragma unroll
            for (int j = 0; j < 4; j++) b[j] = Bs[kk][tx*4 + j];
#pragma unroll
            for (int i = 0; i < 4; i++)
#pragma unroll
                for (int j = 0; j < 4; j++) acc[i][j] += a[i] * b[j];
        }
        __syncthreads();
    }

#pragma unroll
    for (int i = 0; i < 4; i++) {
        int m = bm + ty*4 + i;
        int b = m >> 11;         // m / T
        int t = m & (Tt - 1);
        size_t base = (((size_t)b * Hh + h) * Tt + t) * 64;
#pragma unroll
        for (int j = 0; j < 4; j++)
            out[base + tx*4 + j] = acc[i][j];
    }
}

// ---------------- causal attention: 1 warp per query, K/V tiles in SMEM ----------------
// grid: (T/8, B*H); block 256 (8 warps)
__global__ void attn_kernel() {
    __shared__ float Ks[64][64];
    __shared__ float Vs[64][64];
    int bh   = blockIdx.y;
    int warp = threadIdx.x >> 5;
    int lane = threadIdx.x & 31;
    int qi   = blockIdx.x * 8 + warp;

    const float* qrow = g_q + ((size_t)bh * Tt + qi) * 64;
    float q0 = qrow[2*lane], q1 = qrow[2*lane + 1];

    const float scale = 0.125f; // 1/sqrt(64)
    float m = -1e30f, l = 0.f, o0 = 0.f, o1 = 0.f;

    int qmax = blockIdx.x * 8 + 7;
    for (int s0 = 0; s0 <= qmax; s0 += 64) {
        __syncthreads();
        for (int e = threadIdx.x; e < 64*64; e += 256) {
            int r = e >> 6, c = e & 63;
            size_t gi = ((size_t)bh * Tt + s0 + r) * 64 + c;
            Ks[r][c] = g_k[gi];
            Vs[r][c] = g_v[gi];
        }
        __syncthreads();

        int smax = qi - s0 + 1;
        if (smax > 64) smax = 64;
        for (int s = 0; s < smax; s++) {
            float sc = q0 * Ks[s][2*lane] + q1 * Ks[s][2*lane + 1];
            sc += __shfl_xor_sync(0xffffffffu, sc, 16);
            sc += __shfl_xor_sync(0xffffffffu, sc, 8);
            sc += __shfl_xor_sync(0xffffffffu, sc, 4);
            sc += __shfl_xor_sync(0xffffffffu, sc, 2);
            sc += __shfl_xor_sync(0xffffffffu, sc, 1);
            sc *= scale;
            float mn   = fmaxf(m, sc);
            float corr = __expf(m - mn);
            float p    = __expf(sc - mn);
            l  = l * corr + p;
            o0 = o0 * corr + p * Vs[s][2*lane];
            o1 = o1 * corr + p * Vs[s][2*lane + 1];
            m = mn;
        }
    }

    float inv = 1.f / l;
    size_t base = ((size_t)bh * Tt + qi) * 64;
    g_o[base + 2*lane]     = o0 * inv;
    g_o[base + 2*lane + 1] = o1 * inv;
}

// ---------------- concat heads: [B,H,T,K] -> [B,T,D] ----------------
__global__ void concat_kernel() {
    size_t i = (size_t)blockIdx.x * 256 + threadIdx.x;  // over MR*Dd
    int col = (int)(i & (Dd - 1));
    int row = (int)(i >> 10);
    int h = col >> 6, k = col & 63;
    int b = row >> 11, t = row & (Tt - 1);
    g_oc[i] = g_o[(((size_t)b * Hh + h) * Tt + t) * 64 + k];
}

// ---------------- launch ----------------
extern "C" void kernel_launch(void* const* d_in, const int* in_sizes, int n_in,
                              void* d_out, int out_size) {
    const float* x   = (const float*)d_in[0];
    const float* Wq  = (const float*)d_in[1];
    const float* Wk  = (const float*)d_in[2];
    const float* Wv  = (const float*)d_in[3];
    const float* Wo  = (const float*)d_in[4];
    const float* bo  = (const float*)d_in[5];
    const float* W1  = (const float*)d_in[6];
    const float* b1  = (const float*)d_in[7];
    const float* W2  = (const float*)d_in[8];
    const float* b2  = (const float*)d_in[9];
    const float* g1  = (const float*)d_in[10];
    const float* be1 = (const float*)d_in[11];
    const float* g2  = (const float*)d_in[12];
    const float* be2 = (const float*)d_in[13];
    float* out = (float*)d_out;

    float *p_h, *p_oc, *p_x1, *p_h2, *p_ff;
    cudaGetSymbolAddress((void**)&p_h,  g_h);
    cudaGetSymbolAddress((void**)&p_oc, g_oc);
    cudaGetSymbolAddress((void**)&p_x1, g_x1);
    cudaGetSymbolAddress((void**)&p_h2, g_h2);
    cudaGetSymbolAddress((void**)&p_ff, g_ff);

    // 1. LN1
    ln_kernel<<<MR, 256>>>(x, g1, be1, p_h);
    // 2. QKV projections
    {
        dim3 grid(Hh, MR / 64, 3);
        qkv_kernel<<<grid, 256>>>(p_h, Wq, Wk, Wv);
    }
    // 3. causal attention
    {
        dim3 grid(Tt / 8, Bb * Hh);
        attn_kernel<<<grid, 256>>>();
    }
    // 4. concat heads
    concat_kernel<<<(MR * Dd) / 256, 256>>>();
    // 5. Wo projection + bias + residual -> x1
    {
        dim3 grid(Dd / 64, MR / 64);
        gemm_kernel<<<grid, 256>>>(p_oc, Wo, bo, x, p_x1, MR, Dd, Dd, 3);
    }
    // 6. LN2
    ln_kernel<<<MR, 256>>>(p_x1, g2, be2, p_h2);
    // 7. FFN1: h2 @ W1 + b1, GELU
    {
        dim3 grid(FF / 64, MR / 64);
        gemm_kernel<<<grid, 256>>>(p_h2, W1, b1, nullptr, p_ff, MR, FF, Dd, 5);
    }
    // 8. FFN2: ff @ W2 + b2 + x1 -> out
    {
        dim3 grid(Dd / 64, MR / 64);
        gemm_kernel<<<grid, 256>>>(p_ff, W2, b2, p_x1, out, MR, Dd, FF, 3);
    }
}

// round 4
// speedup vs baseline: 1.7376x; 1.7376x over previous
#include <cuda_runtime.h>
#include <cstdint>
#include <math.h>

#define Bb   2
#define Tt   2048
#define Dd   1024
#define Hh   16
#define FF   4096
#define MR   (Bb*Tt)   // 4096 tokens
#define QKVN 3072

// ---------------- scratch ----------------
__device__ float g_h   [MR*Dd];     // LN1 out (tf32-rounded)
__device__ float g_qkv [MR*QKVN];   // [tok][ q(1024) k(1024) v(1024) ]
__device__ float g_oc  [MR*Dd];     // attention out (tf32-rounded)
__device__ float g_x1  [MR*Dd];     // attn residual (full fp32)
__device__ float g_h2  [MR*Dd];     // LN2 out (tf32-rounded)
__device__ float g_ff  [MR*FF];     // FFN hidden (tf32-rounded)
__device__ float g_wtq [QKVN*Dd];   // fused QKV weights [3072,1024] K-major (tf32)
__device__ float g_wto [Dd*Dd];     // Wo^T (tf32)
__device__ float g_wt1 [FF*Dd];     // W1^T (tf32)
__device__ float g_wt2 [Dd*FF];     // W2^T (tf32)

// ---------------- helpers ----------------
__device__ __forceinline__ float to_tf32(float x) {
    uint32_t u;
    asm("cvt.rna.tf32.f32 %0, %1;" : "=r"(u) : "f"(x));
    return __uint_as_float(u);
}
__device__ __forceinline__ uint32_t smem_u32(const void* p) {
    uint32_t a;
    asm("{ .reg .u64 t; cvta.to.shared.u64 t, %1; cvt.u32.u64 %0, t; }" : "=r"(a) : "l"(p));
    return a;
}
__device__ __forceinline__ void cpasync16(uint32_t dst, const void* src) {
    asm volatile("cp.async.cg.shared.global [%0], [%1], 16;" :: "r"(dst), "l"(src) : "memory");
}
#define CP_COMMIT() asm volatile("cp.async.commit_group;" ::: "memory")
#define CP_WAIT1()  asm volatile("cp.async.wait_group 1;" ::: "memory")
#define CP_WAIT0()  asm volatile("cp.async.wait_group 0;" ::: "memory")

// ---------------- LayerNorm (always rounds output to tf32) ----------------
__global__ void ln_kernel(const float* __restrict__ x, const float* __restrict__ g,
                          const float* __restrict__ be, float* __restrict__ out) {
    __shared__ float red[256];
    int row = blockIdx.x;
    int tid = threadIdx.x;
    const float* xr = x + (size_t)row * Dd;
    float v[4]; float s = 0.f;
#pragma unroll
    for (int i = 0; i < 4; i++) { v[i] = xr[tid + 256*i]; s += v[i]; }
    red[tid] = s; __syncthreads();
    for (int o = 128; o > 0; o >>= 1) { if (tid < o) red[tid] += red[tid + o]; __syncthreads(); }
    float mu = red[0] * (1.f / Dd);
    __syncthreads();
    float sq = 0.f;
#pragma unroll
    for (int i = 0; i < 4; i++) { float d = v[i] - mu; sq += d * d; }
    red[tid] = sq; __syncthreads();
    for (int o = 128; o > 0; o >>= 1) { if (tid < o) red[tid] += red[tid + o]; __syncthreads(); }
    float rstd = rsqrtf(red[0] * (1.f / Dd) + 1e-5f);
    float* orow = out + (size_t)row * Dd;
#pragma unroll
    for (int i = 0; i < 4; i++) {
        int c = tid + 256*i;
        orow[c] = to_tf32((v[i] - mu) * rstd * g[c] + be[c]);
    }
}

// ---------------- transpose (weights; always rounds to tf32) ----------------
__global__ void transpose_kernel(const float* __restrict__ in, float* __restrict__ out,
                                 int R, int C, int ldo, long in_bs, long out_bs) {
    __shared__ float t[32][33];
    const float* ib = in + in_bs * blockIdx.z;
    float* ob = out + out_bs * blockIdx.z;
    int bx = blockIdx.x * 32, by = blockIdx.y * 32;
    int x = threadIdx.x, y = threadIdx.y;
#pragma unroll
    for (int i = 0; i < 4; i++) t[y + 8*i][x] = ib[(size_t)(by + y + 8*i) * C + bx + x];
    __syncthreads();
#pragma unroll
    for (int i = 0; i < 4; i++) ob[(size_t)(bx + y + 8*i) * ldo + by + x] = to_tf32(t[x][y + 8*i]);
}

// ---------------- tf32 mma.sync GEMM: C[M,N] = A[M,K] @ Bt[N,K]^T ----------------
// CTA tile 128x256, 8 warps (2x4) of 64x64 each, BK=32, cp.async double buffer.
// mode bit0: +bias, bit1: +resid, bit2: exact GELU, bit3: round output to tf32
#define BM 128
#define BN 256
#define BK 32
#define LDT 36                       // padded row stride (floats)
#define ABYTES (BM*LDT*4)            // 18432
#define BBYTES (BN*LDT*4)            // 36864
#define GSMEM  (2*(ABYTES + BBYTES)) // 110592

__global__ void __launch_bounds__(256, 1) gemm_mma(
    const float* __restrict__ A, const float* __restrict__ Bt,
    const float* __restrict__ bias, const float* __restrict__ resid,
    float* __restrict__ C, int Kd, int ldc, int mode)
{
    extern __shared__ char smem[];
    float* As = (float*)smem;                      // [2][BM][LDT]
    float* Bs = (float*)(smem + 2 * ABYTES);       // [2][BN][LDT]
    const uint32_t aU = smem_u32(As);
    const uint32_t bU = smem_u32(Bs);

    int tid  = threadIdx.x;
    int wid  = tid >> 5;
    int lane = tid & 31;
    int gid  = lane >> 2;     // group id (0..7)
    int tig  = lane & 3;      // thread in group
    int wm = wid >> 2;        // 0..1
    int wn = wid & 3;         // 0..3
    int bm = blockIdx.y * BM;
    int bn = blockIdx.x * BN;

    float acc[4][8][4];
#pragma unroll
    for (int i = 0; i < 4; i++)
#pragma unroll
        for (int j = 0; j < 8; j++)
#pragma unroll
            for (int k = 0; k < 4; k++) acc[i][j][k] = 0.f;

    const int NC = Kd >> 5;

    // ---- stage chunk 0 ----
    {
        uint32_t ad = aU, bd = bU;
#pragma unroll
        for (int i = 0; i < 4; i++) {
            int idx = tid + 256*i; int m = idx >> 3, ch = idx & 7;
            cpasync16(ad + (m*LDT + ch*4)*4, A + (size_t)(bm + m) * Kd + ch*4);
        }
#pragma unroll
        for (int i = 0; i < 8; i++) {
            int idx = tid + 256*i; int n = idx >> 3, ch = idx & 7;
            cpasync16(bd + (n*LDT + ch*4)*4, Bt + (size_t)(bn + n) * Kd + ch*4);
        }
        CP_COMMIT();
    }

    for (int c = 0; c < NC; c++) {
        if (c + 1 < NC) {
            int nb = (c + 1) & 1;
            int k0 = (c + 1) << 5;
            uint32_t ad = aU + nb * ABYTES, bd = bU + nb * BBYTES;
#pragma unroll
            for (int i = 0; i < 4; i++) {
                int idx = tid + 256*i; int m = idx >> 3, ch = idx & 7;
                cpasync16(ad + (m*LDT + ch*4)*4, A + (size_t)(bm + m) * Kd + k0 + ch*4);
            }
#pragma unroll
            for (int i = 0; i < 8; i++) {
                int idx = tid + 256*i; int n = idx >> 3, ch = idx & 7;
                cpasync16(bd + (n*LDT + ch*4)*4, Bt + (size_t)(bn + n) * Kd + k0 + ch*4);
            }
            CP_COMMIT();
            CP_WAIT1();
        } else {
            CP_WAIT0();
        }
        __syncthreads();

        const float* aB = As + (c & 1) * (BM*LDT);
        const float* bB = Bs + (c & 1) * (BN*LDT);
#pragma unroll
        for (int ks = 0; ks < 4; ks++) {
            int kc = ks*8 + tig;
            uint32_t af[4][4], bf[8][2];
#pragma unroll
            for (int mt = 0; mt < 4; mt++) {
                const float* p = aB + (wm*64 + mt*16 + gid) * LDT + kc;
                af[mt][0] = __float_as_uint(p[0]);
                af[mt][1] = __float_as_uint(p[8*LDT]);
                af[mt][2] = __float_as_uint(p[4]);
                af[mt][3] = __float_as_uint(p[8*LDT + 4]);
            }
#pragma unroll
            for (int nt = 0; nt < 8; nt++) {
                const float* p = bB + (wn*64 + nt*8 + gid) * LDT + kc;
                bf[nt][0] = __float_as_uint(p[0]);
                bf[nt][1] = __float_as_uint(p[4]);
            }
#pragma unroll
            for (int mt = 0; mt < 4; mt++)
#pragma unroll
                for (int nt = 0; nt < 8; nt++) {
                    float* cc = acc[mt][nt];
                    asm volatile(
                        "mma.sync.aligned.m16n8k8.row.col.f32.tf32.tf32.f32 "
                        "{%0,%1,%2,%3}, {%4,%5,%6,%7}, {%8,%9}, {%0,%1,%2,%3};"
                        : "+f"(cc[0]), "+f"(cc[1]), "+f"(cc[2]), "+f"(cc[3])
                        : "r"(af[mt][0]), "r"(af[mt][1]), "r"(af[mt][2]), "r"(af[mt][3]),
                          "r"(bf[nt][0]), "r"(bf[nt][1]));
                }
        }
        __syncthreads();
    }

    // ---- epilogue ----
#pragma unroll
    for (int mt = 0; mt < 4; mt++) {
        int r0 = bm + wm*64 + mt*16 + gid;
        int r1 = r0 + 8;
#pragma unroll
        for (int nt = 0; nt < 8; nt++) {
            int cc = bn + wn*64 + nt*8 + tig*2;
            float v0 = acc[mt][nt][0], v1 = acc[mt][nt][1];
            float v2 = acc[mt][nt][2], v3 = acc[mt][nt][3];
            if (mode & 1) { float b0 = bias[cc], b1 = bias[cc+1]; v0 += b0; v1 += b1; v2 += b0; v3 += b1; }
            if (mode & 2) {
                const float* rr0 = resid + (size_t)r0 * ldc + cc;
                const float* rr1 = resid + (size_t)r1 * ldc + cc;
                v0 += rr0[0]; v1 += rr0[1]; v2 += rr1[0]; v3 += rr1[1];
            }
            if (mode & 4) {
                v0 = 0.5f * v0 * (1.f + erff(v0 * 0.70710678118654752f));
                v1 = 0.5f * v1 * (1.f + erff(v1 * 0.70710678118654752f));
                v2 = 0.5f * v2 * (1.f + erff(v2 * 0.70710678118654752f));
                v3 = 0.5f * v3 * (1.f + erff(v3 * 0.70710678118654752f));
            }
            if (mode & 8) { v0 = to_tf32(v0); v1 = to_tf32(v1); v2 = to_tf32(v2); v3 = to_tf32(v3); }
            *(float2*)(C + (size_t)r0 * ldc + cc) = make_float2(v0, v1);
            *(float2*)(C + (size_t)r1 * ldc + cc) = make_float2(v2, v3);
        }
    }
}

// ---------------- causal attention: 1 warp/query ----------------
__global__ void attn_kernel() {
    __shared__ float Ks[64][64];
    __shared__ float Vs[64][64];
    int bh   = blockIdx.y;
    int b    = bh >> 4, h = bh & 15;
    int warp = threadIdx.x >> 5;
    int lane = threadIdx.x & 31;
    int qi   = blockIdx.x * 8 + warp;

    const float* qrow = g_qkv + ((size_t)(b * Tt + qi)) * QKVN + h * 64;
    float q0 = qrow[2*lane], q1 = qrow[2*lane + 1];

    const float scale = 0.125f;
    float m = -1e30f, l = 0.f, o0 = 0.f, o1 = 0.f;

    int qmax = blockIdx.x * 8 + 7;
    for (int s0 = 0; s0 <= qmax; s0 += 64) {
        __syncthreads();
        for (int e = threadIdx.x; e < 64*64; e += 256) {
            int r = e >> 6, cc = e & 63;
            size_t base = (size_t)(b * Tt + s0 + r) * QKVN + h * 64 + cc;
            Ks[r][cc] = g_qkv[base + 1024];
            Vs[r][cc] = g_qkv[base + 2048];
        }
        __syncthreads();
        int smax = qi - s0 + 1;
        if (smax > 64) smax = 64;
        for (int s = 0; s < smax; s++) {
            float sc = q0 * Ks[s][2*lane] + q1 * Ks[s][2*lane + 1];
            sc += __shfl_xor_sync(0xffffffffu, sc, 16);
            sc += __shfl_xor_sync(0xffffffffu, sc, 8);
            sc += __shfl_xor_sync(0xffffffffu, sc, 4);
            sc += __shfl_xor_sync(0xffffffffu, sc, 2);
            sc += __shfl_xor_sync(0xffffffffu, sc, 1);
            sc *= scale;
            float mn   = fmaxf(m, sc);
            float corr = __expf(m - mn);
            float p    = __expf(sc - mn);
            l  = l * corr + p;
            o0 = o0 * corr + p * Vs[s][2*lane];
            o1 = o1 * corr + p * Vs[s][2*lane + 1];
            m = mn;
        }
    }
    float inv = 1.f / l;
    size_t base = (size_t)(b * Tt + qi) * Dd + h * 64;
    g_oc[base + 2*lane]     = to_tf32(o0 * inv);
    g_oc[base + 2*lane + 1] = to_tf32(o1 * inv);
}

// ---------------- launch ----------------
extern "C" void kernel_launch(void* const* d_in, const int* in_sizes, int n_in,
                              void* d_out, int out_size) {
    const float* x   = (const float*)d_in[0];
    const float* Wq  = (const float*)d_in[1];
    const float* Wk  = (const float*)d_in[2];
    const float* Wv  = (const float*)d_in[3];
    const float* Wo  = (const float*)d_in[4];
    const float* bo  = (const float*)d_in[5];
    const float* W1  = (const float*)d_in[6];
    const float* b1  = (const float*)d_in[7];
    const float* W2  = (const float*)d_in[8];
    const float* b2  = (const float*)d_in[9];
    const float* g1  = (const float*)d_in[10];
    const float* be1 = (const float*)d_in[11];
    const float* g2  = (const float*)d_in[12];
    const float* be2 = (const float*)d_in[13];
    float* out = (float*)d_out;

    float *p_h, *p_qkv, *p_oc, *p_x1, *p_h2, *p_ff, *p_wtq, *p_wto, *p_wt1, *p_wt2;
    cudaGetSymbolAddress((void**)&p_h,   g_h);
    cudaGetSymbolAddress((void**)&p_qkv, g_qkv);
    cudaGetSymbolAddress((void**)&p_oc,  g_oc);
    cudaGetSymbolAddress((void**)&p_x1,  g_x1);
    cudaGetSymbolAddress((void**)&p_h2,  g_h2);
    cudaGetSymbolAddress((void**)&p_ff,  g_ff);
    cudaGetSymbolAddress((void**)&p_wtq, g_wtq);
    cudaGetSymbolAddress((void**)&p_wto, g_wto);
    cudaGetSymbolAddress((void**)&p_wt1, g_wt1);
    cudaGetSymbolAddress((void**)&p_wt2, g_wt2);

    cudaFuncSetAttribute(gemm_mma, cudaFuncAttributeMaxDynamicSharedMemorySize, GSMEM);

    dim3 tb(32, 8);
    transpose_kernel<<<dim3(2, 32, Hh), tb>>>(Wq, p_wtq,           Dd, 64, Dd, (long)Dd*64, 64L*Dd);
    transpose_kernel<<<dim3(2, 32, Hh), tb>>>(Wk, p_wtq + 1024*Dd, Dd, 64, Dd, (long)Dd*64, 64L*Dd);
    transpose_kernel<<<dim3(2, 32, Hh), tb>>>(Wv, p_wtq + 2048*Dd, Dd, 64, Dd, (long)Dd*64, 64L*Dd);
    transpose_kernel<<<dim3(32, 32, 1), tb>>>(Wo, p_wto, Dd, Dd, Dd, 0, 0);
    transpose_kernel<<<dim3(FF/32, 32, 1), tb>>>(W1, p_wt1, Dd, FF, Dd, 0, 0);
    transpose_kernel<<<dim3(32, FF/32, 1), tb>>>(W2, p_wt2, FF, Dd, FF, 0, 0);

    // 1. LN1
    ln_kernel<<<MR, 256>>>(x, g1, be1, p_h);
    // 2. fused QKV GEMM
    gemm_mma<<<dim3(QKVN/BN, MR/BM), 256, GSMEM>>>(p_h, p_wtq, nullptr, nullptr, p_qkv, Dd, QKVN, 0);
    // 3. attention
    attn_kernel<<<dim3(Tt/8, Bb*Hh), 256>>>();
    // 4. Wo + bias + residual(x) -> x1 (full fp32)
    gemm_mma<<<dim3(Dd/BN, MR/BM), 256, GSMEM>>>(p_oc, p_wto, bo, x, p_x1, Dd, Dd, 3);
    // 5. LN2
    ln_kernel<<<MR, 256>>>(p_x1, g2, be2, p_h2);
    // 6. FFN1 + bias + GELU, round to tf32
    gemm_mma<<<dim3(FF/BN, MR/BM), 256, GSMEM>>>(p_h2, p_wt1, b1, nullptr, p_ff, Dd, FF, 13);
    // 7. FFN2 + bias + residual(x1) -> out
    gemm_mma<<<dim3(Dd/BN, MR/BM), 256, GSMEM>>>(p_ff, p_wt2, b2, p_x1, out, FF, Dd, 3);
}

// round 7
// speedup vs baseline: 5.2408x; 3.0161x over previous
#include <cuda_runtime.h>
#include <cstdint>
#include <math.h>

#define Bb   2
#define Tt   2048
#define Dd   1024
#define Hh   16
#define FF   4096
#define MR   (Bb*Tt)   // 4096 tokens
#define QKVN 3072

// ---------------- scratch ----------------
__device__ float g_h   [MR*Dd];     // LN1 out (tf32-rounded)
__device__ float g_qkv [MR*QKVN];   // [tok][ q(1024) k(1024) v(1024) ]
__device__ float g_oc  [MR*Dd];     // attention out
__device__ float g_x1  [MR*Dd];     // attn residual (full fp32)
__device__ float g_h2  [MR*Dd];     // LN2 out (tf32-rounded)
__device__ float g_ff  [MR*FF];     // FFN hidden
__device__ float g_wtq [QKVN*Dd];   // fused QKV weights [3072,1024] K-major (tf32)
__device__ float g_wto [Dd*Dd];     // Wo^T (tf32)
__device__ float g_wt1 [FF*Dd];     // W1^T (tf32)
__device__ float g_wt2 [Dd*FF];     // W2^T (tf32)

// ---------------- helpers ----------------
__device__ __forceinline__ float to_tf32(float x) {
    uint32_t u;
    asm("cvt.rna.tf32.f32 %0, %1;" : "=r"(u) : "f"(x));
    return __uint_as_float(u);
}
__device__ __forceinline__ uint32_t smem_u32(const void* p) {
    uint32_t a;
    asm("{ .reg .u64 t; cvta.to.shared.u64 t, %1; cvt.u32.u64 %0, t; }" : "=r"(a) : "l"(p));
    return a;
}
__device__ __forceinline__ void cpasync16(uint32_t dst, const void* src) {
    asm volatile("cp.async.cg.shared.global [%0], [%1], 16;" :: "r"(dst), "l"(src) : "memory");
}
#define CP_COMMIT() asm volatile("cp.async.commit_group;" ::: "memory")
#define CP_WAIT1()  asm volatile("cp.async.wait_group 1;" ::: "memory")
#define CP_WAIT0()  asm volatile("cp.async.wait_group 0;" ::: "memory")

// fast exp on FFMA pipe (x <= 0 path; exact at 0; flushes huge-negative to 0)
__device__ __forceinline__ float fexp(float x) {
    float y = x * 1.44269504f;
    if (y < -126.f) return 0.f;
    float yi = floorf(y);
    float f = y - yi;
    float p = 1.f + f*(0.6931472f + f*(0.2402265f + f*(0.0554943f + f*(0.0096181f + f*0.0013333f))));
    return p * __int_as_float(((int)yi + 127) << 23);
}

#define MMA_TF32(c0,c1,c2,c3,a0,a1,a2,a3,b0,b1) \
    asm volatile("mma.sync.aligned.m16n8k8.row.col.f32.tf32.tf32.f32 " \
        "{%0,%1,%2,%3}, {%4,%5,%6,%7}, {%8,%9}, {%0,%1,%2,%3};" \
        : "+f"(c0), "+f"(c1), "+f"(c2), "+f"(c3) \
        : "r"(a0), "r"(a1), "r"(a2), "r"(a3), "r"(b0), "r"(b1))

// ---------------- LayerNorm (rounds output to tf32) ----------------
__global__ void ln_kernel(const float* __restrict__ x, const float* __restrict__ g,
                          const float* __restrict__ be, float* __restrict__ out) {
    __shared__ float red[256];
    int row = blockIdx.x;
    int tid = threadIdx.x;
    const float* xr = x + (size_t)row * Dd;
    float v[4]; float s = 0.f;
#pragma unroll
    for (int i = 0; i < 4; i++) { v[i] = xr[tid + 256*i]; s += v[i]; }
    red[tid] = s; __syncthreads();
    for (int o = 128; o > 0; o >>= 1) { if (tid < o) red[tid] += red[tid + o]; __syncthreads(); }
    float mu = red[0] * (1.f / Dd);
    __syncthreads();
    float sq = 0.f;
#pragma unroll
    for (int i = 0; i < 4; i++) { float d = v[i] - mu; sq += d * d; }
    red[tid] = sq; __syncthreads();
    for (int o = 128; o > 0; o >>= 1) { if (tid < o) red[tid] += red[tid + o]; __syncthreads(); }
    float rstd = rsqrtf(red[0] * (1.f / Dd) + 1e-5f);
    float* orow = out + (size_t)row * Dd;
#pragma unroll
    for (int i = 0; i < 4; i++) {
        int c = tid + 256*i;
        orow[c] = to_tf32((v[i] - mu) * rstd * g[c] + be[c]);
    }
}

// ---------------- transpose (weights; rounds to tf32) ----------------
__global__ void transpose_kernel(const float* __restrict__ in, float* __restrict__ out,
                                 int R, int C, int ldo, long in_bs, long out_bs) {
    __shared__ float t[32][33];
    const float* ib = in + in_bs * blockIdx.z;
    float* ob = out + out_bs * blockIdx.z;
    int bx = blockIdx.x * 32, by = blockIdx.y * 32;
    int x = threadIdx.x, y = threadIdx.y;
#pragma unroll
    for (int i = 0; i < 4; i++) t[y + 8*i][x] = ib[(size_t)(by + y + 8*i) * C + bx + x];
    __syncthreads();
#pragma unroll
    for (int i = 0; i < 4; i++) ob[(size_t)(bx + y + 8*i) * ldo + by + x] = to_tf32(t[x][y + 8*i]);
}

// ---------------- tf32 mma.sync GEMM (validated round 4) ----------------
#define BM 128
#define BN 256
#define LDT 36
#define ABYTES (BM*LDT*4)
#define BBYTES (BN*LDT*4)
#define GSMEM  (2*(ABYTES + BBYTES))

__global__ void __launch_bounds__(256, 1) gemm_mma(
    const float* __restrict__ A, const float* __restrict__ Bt,
    const float* __restrict__ bias, const float* __restrict__ resid,
    float* __restrict__ C, int Kd, int ldc, int mode)
{
    extern __shared__ char smem[];
    float* As = (float*)smem;
    float* Bs = (float*)(smem + 2 * ABYTES);
    const uint32_t aU = smem_u32(As);
    const uint32_t bU = smem_u32(Bs);

    int tid  = threadIdx.x;
    int wid  = tid >> 5;
    int lane = tid & 31;
    int gid  = lane >> 2;
    int tig  = lane & 3;
    int wm = wid >> 2;
    int wn = wid & 3;
    int bm = blockIdx.y * BM;
    int bn = blockIdx.x * BN;

    float acc[4][8][4];
#pragma unroll
    for (int i = 0; i < 4; i++)
#pragma unroll
        for (int j = 0; j < 8; j++)
#pragma unroll
            for (int k = 0; k < 4; k++) acc[i][j][k] = 0.f;

    const int NC = Kd >> 5;

    {
#pragma unroll
        for (int i = 0; i < 4; i++) {
            int idx = tid + 256*i; int m = idx >> 3, ch = idx & 7;
            cpasync16(aU + (m*LDT + ch*4)*4, A + (size_t)(bm + m) * Kd + ch*4);
        }
#pragma unroll
        for (int i = 0; i < 8; i++) {
            int idx = tid + 256*i; int n = idx >> 3, ch = idx & 7;
            cpasync16(bU + (n*LDT + ch*4)*4, Bt + (size_t)(bn + n) * Kd + ch*4);
        }
        CP_COMMIT();
    }

    for (int c = 0; c < NC; c++) {
        if (c + 1 < NC) {
            int nb = (c + 1) & 1;
            int k0 = (c + 1) << 5;
            uint32_t ad = aU + nb * ABYTES, bd = bU + nb * BBYTES;
#pragma unroll
            for (int i = 0; i < 4; i++) {
                int idx = tid + 256*i; int m = idx >> 3, ch = idx & 7;
                cpasync16(ad + (m*LDT + ch*4)*4, A + (size_t)(bm + m) * Kd + k0 + ch*4);
            }
#pragma unroll
            for (int i = 0; i < 8; i++) {
                int idx = tid + 256*i; int n = idx >> 3, ch = idx & 7;
                cpasync16(bd + (n*LDT + ch*4)*4, Bt + (size_t)(bn + n) * Kd + k0 + ch*4);
            }
            CP_COMMIT();
            CP_WAIT1();
        } else {
            CP_WAIT0();
        }
        __syncthreads();

        const float* aB = As + (c & 1) * (BM*LDT);
        const float* bB = Bs + (c & 1) * (BN*LDT);
#pragma unroll
        for (int ks = 0; ks < 4; ks++) {
            int kc = ks*8 + tig;
            uint32_t af[4][4], bf[8][2];
#pragma unroll
            for (int mt = 0; mt < 4; mt++) {
                const float* p = aB + (wm*64 + mt*16 + gid) * LDT + kc;
                af[mt][0] = __float_as_uint(p[0]);
                af[mt][1] = __float_as_uint(p[8*LDT]);
                af[mt][2] = __float_as_uint(p[4]);
                af[mt][3] = __float_as_uint(p[8*LDT + 4]);
            }
#pragma unroll
            for (int nt = 0; nt < 8; nt++) {
                const float* p = bB + (wn*64 + nt*8 + gid) * LDT + kc;
                bf[nt][0] = __float_as_uint(p[0]);
                bf[nt][1] = __float_as_uint(p[4]);
            }
#pragma unroll
            for (int mt = 0; mt < 4; mt++)
#pragma unroll
                for (int nt = 0; nt < 8; nt++)
                    MMA_TF32(acc[mt][nt][0], acc[mt][nt][1], acc[mt][nt][2], acc[mt][nt][3],
                             af[mt][0], af[mt][1], af[mt][2], af[mt][3], bf[nt][0], bf[nt][1]);
        }
        __syncthreads();
    }

#pragma unroll
    for (int mt = 0; mt < 4; mt++) {
        int r0 = bm + wm*64 + mt*16 + gid;
        int r1 = r0 + 8;
#pragma unroll
        for (int nt = 0; nt < 8; nt++) {
            int cc = bn + wn*64 + nt*8 + tig*2;
            float v0 = acc[mt][nt][0], v1 = acc[mt][nt][1];
            float v2 = acc[mt][nt][2], v3 = acc[mt][nt][3];
            if (mode & 1) { float b0 = bias[cc], b1 = bias[cc+1]; v0 += b0; v1 += b1; v2 += b0; v3 += b1; }
            if (mode & 2) {
                const float* rr0 = resid + (size_t)r0 * ldc + cc;
                const float* rr1 = resid + (size_t)r1 * ldc + cc;
                v0 += rr0[0]; v1 += rr0[1]; v2 += rr1[0]; v3 += rr1[1];
            }
            if (mode & 4) {
                v0 = 0.5f * v0 * (1.f + erff(v0 * 0.70710678118654752f));
                v1 = 0.5f * v1 * (1.f + erff(v1 * 0.70710678118654752f));
                v2 = 0.5f * v2 * (1.f + erff(v2 * 0.70710678118654752f));
                v3 = 0.5f * v3 * (1.f + erff(v3 * 0.70710678118654752f));
            }
            if (mode & 8) { v0 = to_tf32(v0); v1 = to_tf32(v1); v2 = to_tf32(v2); v3 = to_tf32(v3); }
            *(float2*)(C + (size_t)r0 * ldc + cc) = make_float2(v0, v1);
            *(float2*)(C + (size_t)r1 * ldc + cc) = make_float2(v2, v3);
        }
    }
}

// ---------------- mma-based causal flash attention ----------------
// block: 128 threads (4 warps), 64 q rows of one (b,h). warp w owns rows 16w..16w+15.
#define LDP 68
#define ASMEM (4*64*LDP*4)   // Qs,Ks,Vt,Ps = 69632 B

__global__ void __launch_bounds__(128, 2) attn_mma() {
    extern __shared__ char asm_smem[];
    float* Qs = (float*)asm_smem;
    float* Ks = Qs + 64*LDP;
    float* Vt = Ks + 64*LDP;
    float* Ps = Vt + 64*LDP;

    int bh = blockIdx.y;
    int b = bh >> 4, h = bh & 15;
    int q0 = blockIdx.x * 64;
    int tid = threadIdx.x;
    int w = tid >> 5, lane = tid & 31;
    int gid = lane >> 2, tig = lane & 3;

    const float* qkv = g_qkv;

    // stage Q (pre-scaled by 1/8)
#pragma unroll
    for (int i = 0; i < 8; i++) {
        int e = tid + 128*i; int r = e >> 4, c4 = e & 15;
        float4 v = *(const float4*)(qkv + (size_t)(b*Tt + q0 + r) * QKVN + h*64 + c4*4);
        float* d = Qs + r*LDP + c4*4;
        d[0] = v.x * 0.125f; d[1] = v.y * 0.125f; d[2] = v.z * 0.125f; d[3] = v.w * 0.125f;
    }
    __syncthreads();

    // Q fragments (whole block lifetime)
    uint32_t qa[8][4];
#pragma unroll
    for (int ks = 0; ks < 8; ks++) {
        const float* p = Qs + (16*w + gid) * LDP + 8*ks + tig;
        qa[ks][0] = __float_as_uint(p[0]);
        qa[ks][1] = __float_as_uint(p[8*LDP]);
        qa[ks][2] = __float_as_uint(p[4]);
        qa[ks][3] = __float_as_uint(p[8*LDP+4]);
    }

    float of[8][4];
#pragma unroll
    for (int i = 0; i < 8; i++) { of[i][0]=0.f; of[i][1]=0.f; of[i][2]=0.f; of[i][3]=0.f; }
    float m0 = -1e30f, m1 = -1e30f, l0 = 0.f, l1 = 0.f;

    for (int s0 = 0; s0 <= q0; s0 += 64) {
        __syncthreads();
        // stage K [s][k]
#pragma unroll
        for (int i = 0; i < 8; i++) {
            int e = tid + 128*i; int r = e >> 4, c4 = e & 15;
            float4 v = *(const float4*)(qkv + (size_t)(b*Tt + s0 + r) * QKVN + 1024 + h*64 + c4*4);
            float* d = Ks + r*LDP + c4*4;
            d[0] = v.x; d[1] = v.y; d[2] = v.z; d[3] = v.w;
        }
        // stage V transposed: Vt[d][s]
        {
            int r = tid & 63;
            int c4b = (tid >> 6) * 8;
#pragma unroll
            for (int j = 0; j < 8; j++) {
                int c4 = c4b + j;
                float4 v = *(const float4*)(qkv + (size_t)(b*Tt + s0 + r) * QKVN + 2048 + h*64 + c4*4);
                Vt[(4*c4+0)*LDP + r] = v.x;
                Vt[(4*c4+1)*LDP + r] = v.y;
                Vt[(4*c4+2)*LDP + r] = v.z;
                Vt[(4*c4+3)*LDP + r] = v.w;
            }
        }
        __syncthreads();

        // S = Q @ K^T (scaled)
        float sf[8][4];
#pragma unroll
        for (int nt = 0; nt < 8; nt++) {
            float c0=0.f, c1=0.f, c2=0.f, c3=0.f;
#pragma unroll
            for (int ks = 0; ks < 8; ks++) {
                const float* p = Ks + (8*nt + gid) * LDP + 8*ks + tig;
                uint32_t b0 = __float_as_uint(p[0]);
                uint32_t b1 = __float_as_uint(p[4]);
                MMA_TF32(c0, c1, c2, c3, qa[ks][0], qa[ks][1], qa[ks][2], qa[ks][3], b0, b1);
            }
            sf[nt][0]=c0; sf[nt][1]=c1; sf[nt][2]=c2; sf[nt][3]=c3;
        }

        // causal mask on diagonal tile
        if (s0 == q0) {
            int r0 = 16*w + gid, r1 = r0 + 8;
#pragma unroll
            for (int nt = 0; nt < 8; nt++) {
                int c0c = 8*nt + 2*tig, c1c = c0c + 1;
                if (c0c > r0) sf[nt][0] = -1e30f;
                if (c1c > r0) sf[nt][1] = -1e30f;
                if (c0c > r1) sf[nt][2] = -1e30f;
                if (c1c > r1) sf[nt][3] = -1e30f;
            }
        }

        // row maxes
        float mx0 = -1e30f, mx1 = -1e30f;
#pragma unroll
        for (int nt = 0; nt < 8; nt++) {
            mx0 = fmaxf(mx0, fmaxf(sf[nt][0], sf[nt][1]));
            mx1 = fmaxf(mx1, fmaxf(sf[nt][2], sf[nt][3]));
        }
        mx0 = fmaxf(mx0, __shfl_xor_sync(0xffffffffu, mx0, 1));
        mx0 = fmaxf(mx0, __shfl_xor_sync(0xffffffffu, mx0, 2));
        mx1 = fmaxf(mx1, __shfl_xor_sync(0xffffffffu, mx1, 1));
        mx1 = fmaxf(mx1, __shfl_xor_sync(0xffffffffu, mx1, 2));

        float mn0 = fmaxf(m0, mx0), mn1 = fmaxf(m1, mx1);
        float cr0 = fexp(m0 - mn0), cr1 = fexp(m1 - mn1);
        m0 = mn0; m1 = mn1;

        // exponentiate, row sums, store P
        float rs0 = 0.f, rs1 = 0.f;
        float* pr0 = Ps + (16*w + gid) * LDP + 2*tig;
        float* pr1 = pr0 + 8*LDP;
#pragma unroll
        for (int nt = 0; nt < 8; nt++) {
            float p0 = fexp(sf[nt][0] - mn0);
            float p1 = fexp(sf[nt][1] - mn0);
            float p2 = fexp(sf[nt][2] - mn1);
            float p3 = fexp(sf[nt][3] - mn1);
            rs0 += p0 + p1; rs1 += p2 + p3;
            *(float2*)(pr0 + 8*nt) = make_float2(p0, p1);
            *(float2*)(pr1 + 8*nt) = make_float2(p2, p3);
        }
        rs0 += __shfl_xor_sync(0xffffffffu, rs0, 1);
        rs0 += __shfl_xor_sync(0xffffffffu, rs0, 2);
        rs1 += __shfl_xor_sync(0xffffffffu, rs1, 1);
        rs1 += __shfl_xor_sync(0xffffffffu, rs1, 2);
        l0 = l0 * cr0 + rs0;
        l1 = l1 * cr1 + rs1;

        // rescale O
#pragma unroll
        for (int nt = 0; nt < 8; nt++) {
            of[nt][0] *= cr0; of[nt][1] *= cr0;
            of[nt][2] *= cr1; of[nt][3] *= cr1;
        }

        __syncwarp();

        // P fragments
        uint32_t pa[8][4];
#pragma unroll
        for (int sc = 0; sc < 8; sc++) {
            const float* p = Ps + (16*w + gid) * LDP + 8*sc + tig;
            pa[sc][0] = __float_as_uint(p[0]);
            pa[sc][1] = __float_as_uint(p[8*LDP]);
            pa[sc][2] = __float_as_uint(p[4]);
            pa[sc][3] = __float_as_uint(p[8*LDP+4]);
        }

        // O += P @ V   (Vt[d][s] is the col-major B operand)
#pragma unroll
        for (int nt = 0; nt < 8; nt++) {
#pragma unroll
            for (int sc = 0; sc < 8; sc++) {
                const float* p = Vt + (8*nt + gid) * LDP + 8*sc + tig;
                uint32_t b0 = __float_as_uint(p[0]);
                uint32_t b1 = __float_as_uint(p[4]);
                MMA_TF32(of[nt][0], of[nt][1], of[nt][2], of[nt][3],
                         pa[sc][0], pa[sc][1], pa[sc][2], pa[sc][3], b0, b1);
            }
        }
    }

    // write O
    float inv0 = 1.f / l0, inv1 = 1.f / l1;
    int r0 = q0 + 16*w + gid, r1 = r0 + 8;
#pragma unroll
    for (int nt = 0; nt < 8; nt++) {
        int cc = h*64 + 8*nt + 2*tig;
        *(float2*)(g_oc + (size_t)(b*Tt + r0) * Dd + cc) = make_float2(of[nt][0]*inv0, of[nt][1]*inv0);
        *(float2*)(g_oc + (size_t)(b*Tt + r1) * Dd + cc) = make_float2(of[nt][2]*inv1, of[nt][3]*inv1);
    }
}

// ---------------- launch ----------------
extern "C" void kernel_launch(void* const* d_in, const int* in_sizes, int n_in,
                              void* d_out, int out_size) {
    const float* x   = (const float*)d_in[0];
    const float* Wq  = (const float*)d_in[1];
    const float* Wk  = (const float*)d_in[2];
    const float* Wv  = (const float*)d_in[3];
    const float* Wo  = (const float*)d_in[4];
    const float* bo  = (const float*)d_in[5];
    const float* W1  = (const float*)d_in[6];
    const float* b1  = (const float*)d_in[7];
    const float* W2  = (const float*)d_in[8];
    const float* b2  = (const float*)d_in[9];
    const float* g1  = (const float*)d_in[10];
    const float* be1 = (const float*)d_in[11];
    const float* g2  = (const float*)d_in[12];
    const float* be2 = (const float*)d_in[13];
    float* out = (float*)d_out;

    float *p_h, *p_qkv, *p_oc, *p_x1, *p_h2, *p_ff, *p_wtq, *p_wto, *p_wt1, *p_wt2;
    cudaGetSymbolAddress((void**)&p_h,   g_h);
    cudaGetSymbolAddress((void**)&p_qkv, g_qkv);
    cudaGetSymbolAddress((void**)&p_oc,  g_oc);
    cudaGetSymbolAddress((void**)&p_x1,  g_x1);
    cudaGetSymbolAddress((void**)&p_h2,  g_h2);
    cudaGetSymbolAddress((void**)&p_ff,  g_ff);
    cudaGetSymbolAddress((void**)&p_wtq, g_wtq);
    cudaGetSymbolAddress((void**)&p_wto, g_wto);
    cudaGetSymbolAddress((void**)&p_wt1, g_wt1);
    cudaGetSymbolAddress((void**)&p_wt2, g_wt2);

    cudaFuncSetAttribute(gemm_mma, cudaFuncAttributeMaxDynamicSharedMemorySize, GSMEM);
    cudaFuncSetAttribute(attn_mma, cudaFuncAttributeMaxDynamicSharedMemorySize, ASMEM);

    dim3 tb(32, 8);
    // launches 1-5, so launch 6 (ncu -s 5 -c 1 capture) = QKV GEMM
    transpose_kernel<<<dim3(2, 32, Hh), tb>>>(Wq, p_wtq,           Dd, 64, Dd, (long)Dd*64, 64L*Dd);
    transpose_kernel<<<dim3(2, 32, Hh), tb>>>(Wk, p_wtq + 1024*Dd, Dd, 64, Dd, (long)Dd*64, 64L*Dd);
    transpose_kernel<<<dim3(2, 32, Hh), tb>>>(Wv, p_wtq + 2048*Dd, Dd, 64, Dd, (long)Dd*64, 64L*Dd);
    transpose_kernel<<<dim3(32, 32, 1), tb>>>(Wo, p_wto, Dd, Dd, Dd, 0, 0);
    ln_kernel<<<MR, 256>>>(x, g1, be1, p_h);
    // #6: fused QKV GEMM (profiled)
    gemm_mma<<<dim3(QKVN/BN, MR/BM), 256, GSMEM>>>(p_h, p_wtq, nullptr, nullptr, p_qkv, Dd, QKVN, 0);
    // attention
    attn_mma<<<dim3(Tt/64, Bb*Hh), 128, ASMEM>>>();
    // remaining weight transposes
    transpose_kernel<<<dim3(FF/32, 32, 1), tb>>>(W1, p_wt1, Dd, FF, Dd, 0, 0);
    transpose_kernel<<<dim3(32, FF/32, 1), tb>>>(W2, p_wt2, FF, Dd, FF, 0, 0);
    // Wo + bias + residual(x) -> x1
    gemm_mma<<<dim3(Dd/BN, MR/BM), 256, GSMEM>>>(p_oc, p_wto, bo, x, p_x1, Dd, Dd, 3);
    // LN2
    ln_kernel<<<MR, 256>>>(p_x1, g2, be2, p_h2);
    // FFN1 + bias + GELU
    gemm_mma<<<dim3(FF/BN, MR/BM), 256, GSMEM>>>(p_h2, p_wt1, b1, nullptr, p_ff, Dd, FF, 13);
    // FFN2 + bias + residual(x1)
    gemm_mma<<<dim3(Dd/BN, MR/BM), 256, GSMEM>>>(p_ff, p_wt2, b2, p_x1, out, FF, Dd, 3);
}